// round 1
// baseline (speedup 1.0000x reference)
#include <cuda_runtime.h>
#include <math.h>

// Problem dims
#define BSZ   16
#define HH    64
#define WWID  64
#define CDIM  512
#define NHEAD 8
#define DKK   64
#define DVV   64
#define PIX   4096              // HH*WWID
#define MROWS 65536             // BSZ*PIX
#define NKV   512               // NHEAD*DKK

// ---------------- scratch (device globals; no runtime allocation) ----------
__device__ float g_partial[BSZ * 8 * CDIM];        // pooled partial sums
__device__ float g_q[BSZ * NHEAD * DKK];           // pooled queries
__device__ float g_K[(size_t)MROWS * NKV];         // K projection
__device__ float g_V[(size_t)MROWS * NKV];         // V projection
__device__ float g_Ah[BSZ * NHEAD * HH * DVV];     // row-attended values
__device__ float g_Av[BSZ * NHEAD * WWID * DVV];   // col-attended values
__device__ float g_A[(size_t)MROWS * DVV];         // combined pre-projection

// ---------------- 1) spatial mean pooling (partials) -----------------------
__global__ void pool_kernel(const float* __restrict__ x) {
    int b = blockIdx.x, j = blockIdx.y, c = threadIdx.x;
    const float* xp = x + ((size_t)b * PIX + (size_t)j * 512) * CDIM + c;
    float s = 0.f;
#pragma unroll 8
    for (int p = 0; p < 512; p++) s += xp[(size_t)p * CDIM];
    g_partial[(b * 8 + j) * CDIM + c] = s;
}

// ---------------- 2) q = pooled @ Wq + bq -----------------------------------
__global__ void q_kernel(const float* __restrict__ Wq, const float* __restrict__ bq) {
    int b = blockIdx.x, t = threadIdx.x;   // 512 threads
    __shared__ float sp[CDIM];
    float s = 0.f;
#pragma unroll
    for (int j = 0; j < 8; j++) s += g_partial[(b * 8 + j) * CDIM + t];
    sp[t] = s * (1.0f / 4096.0f);
    __syncthreads();
    float acc = bq[t];
#pragma unroll 8
    for (int c = 0; c < CDIM; c++) acc += sp[c] * Wq[c * 512 + t];
    g_q[b * 512 + t] = acc;
}

// ---------------- 3) fp32 SGEMM, C[M,N] = A[M,K]@B[K,N] + bias --------------
// BM=BN=128, BK=8, 256 threads, 8x8 microtile, float4 global & shared loads.
__global__ __launch_bounds__(256) void sgemm_bias(
    int M, int N, int Kd,
    const float* __restrict__ A, const float* __restrict__ Bm,
    const float* __restrict__ bias, float* __restrict__ Cm)
{
    const int BM = 128, BN = 128, BK = 8, TM = 8, TN = 8;
    __shared__ float As[BK][BM];
    __shared__ float Bs[BK][BN];
    int tid = threadIdx.x;
    int bx = blockIdx.x, by = blockIdx.y;
    int tcol = tid & 15;       // 16 thread-cols
    int trow = tid >> 4;       // 16 thread-rows
    int aRow = tid >> 1, aCol = (tid & 1) * 4;
    int bRow = tid >> 5, bCol = (tid & 31) * 4;

    const float* Ag = A + (size_t)by * BM * Kd;
    const float* Bg = Bm + (size_t)bx * BN;

    float acc[TM][TN];
#pragma unroll
    for (int i = 0; i < TM; i++)
#pragma unroll
        for (int j = 0; j < TN; j++) acc[i][j] = 0.f;

    for (int k0 = 0; k0 < Kd; k0 += BK) {
        float4 av = *(const float4*)(Ag + (size_t)aRow * Kd + k0 + aCol);
        As[aCol + 0][aRow] = av.x;
        As[aCol + 1][aRow] = av.y;
        As[aCol + 2][aRow] = av.z;
        As[aCol + 3][aRow] = av.w;
        *(float4*)(&Bs[bRow][bCol]) =
            *(const float4*)(Bg + (size_t)(k0 + bRow) * N + bCol);
        __syncthreads();
#pragma unroll
        for (int k = 0; k < BK; k++) {
            float4 a0 = *(const float4*)(&As[k][trow * TM]);
            float4 a1 = *(const float4*)(&As[k][trow * TM + 4]);
            float4 b0 = *(const float4*)(&Bs[k][tcol * TN]);
            float4 b1 = *(const float4*)(&Bs[k][tcol * TN + 4]);
            float ar[8] = {a0.x, a0.y, a0.z, a0.w, a1.x, a1.y, a1.z, a1.w};
            float br[8] = {b0.x, b0.y, b0.z, b0.w, b1.x, b1.y, b1.z, b1.w};
#pragma unroll
            for (int i = 0; i < TM; i++)
#pragma unroll
                for (int j = 0; j < TN; j++) acc[i][j] += ar[i] * br[j];
        }
        __syncthreads();
    }

    int colBase = bx * BN + tcol * TN;
    float bb[TN];
#pragma unroll
    for (int j = 0; j < TN; j++) bb[j] = bias[colBase + j];
#pragma unroll
    for (int i = 0; i < TM; i++) {
        size_t row = (size_t)by * BM + trow * TM + i;
        float4 o0 = {acc[i][0] + bb[0], acc[i][1] + bb[1],
                     acc[i][2] + bb[2], acc[i][3] + bb[3]};
        float4 o1 = {acc[i][4] + bb[4], acc[i][5] + bb[5],
                     acc[i][6] + bb[6], acc[i][7] + bb[7]};
        *(float4*)(Cm + row * N + colBase)     = o0;
        *(float4*)(Cm + row * N + colBase + 4) = o1;
    }
}

// ---------------- 4) scores + dual softmax + A_h / A_v per (b, head) -------
__global__ __launch_bounds__(256) void attn_kernel() {
    int b = blockIdx.x >> 3, n = blockIdx.x & 7;
    int tid = threadIdx.x, w = tid >> 5, l = tid & 31;

    __shared__ float sq[64];
    __shared__ float ss[4096];   // scores, later attn_v (in place)
    __shared__ float sah[4096];  // attn_h

    if (tid < 64) sq[tid] = g_q[(b * NHEAD + n) * DKK + tid];
    __syncthreads();

    const float scale = 0.125f;  // 1/sqrt(64)
    const float* Kb = g_K + (size_t)b * PIX * NKV + n * DKK;

    // scores: one warp per pixel-slice, lane-parallel dot(q, K_row)
    for (int p = w; p < PIX; p += 8) {
        const float* kr = Kb + (size_t)p * NKV;
        float part = kr[l] * sq[l] + kr[32 + l] * sq[32 + l];
#pragma unroll
        for (int o = 16; o > 0; o >>= 1)
            part += __shfl_xor_sync(0xffffffffu, part, o);
        if (l == 0) ss[p] = part * scale;
    }
    __syncthreads();

    // row softmax over w -> sah
    for (int h = w; h < 64; h += 8) {
        float x0 = ss[h * 64 + l], x1 = ss[h * 64 + 32 + l];
        float m = fmaxf(x0, x1);
#pragma unroll
        for (int o = 16; o > 0; o >>= 1)
            m = fmaxf(m, __shfl_xor_sync(0xffffffffu, m, o));
        float e0 = __expf(x0 - m), e1 = __expf(x1 - m);
        float sum = e0 + e1;
#pragma unroll
        for (int o = 16; o > 0; o >>= 1)
            sum += __shfl_xor_sync(0xffffffffu, sum, o);
        float inv = 1.0f / sum;
        sah[h * 64 + l]      = e0 * inv;
        sah[h * 64 + 32 + l] = e1 * inv;
    }
    __syncthreads();

    // column softmax over h, in place into ss (thread-per-column, conflict-free)
    if (tid < 64) {
        int c = tid;
        float m = -1e30f;
#pragma unroll 8
        for (int h = 0; h < 64; h++) m = fmaxf(m, ss[h * 64 + c]);
        float sum = 0.f;
#pragma unroll 8
        for (int h = 0; h < 64; h++) sum += __expf(ss[h * 64 + c] - m);
        float inv = 1.0f / sum;
#pragma unroll 8
        for (int h = 0; h < 64; h++)
            ss[h * 64 + c] = __expf(ss[h * 64 + c] - m) * inv;
    }
    __syncthreads();

    const float* Vb = g_V + (size_t)b * PIX * NKV + n * DKK;
    float* Ahp = g_Ah + (size_t)(b * NHEAD + n) * HH * DVV;
    float* Avp = g_Av + (size_t)(b * NHEAD + n) * WWID * DVV;

    // A_h[h,v] = sum_w attn_h[h,w] * V[(h,w),v]   (warp owns h rows)
    for (int h = w; h < 64; h += 8) {
        float a0 = 0.f, a1 = 0.f;
#pragma unroll 4
        for (int wc = 0; wc < 64; wc++) {
            float aw = sah[h * 64 + wc];
            const float* vr = Vb + (size_t)(h * 64 + wc) * NKV;
            a0 += aw * vr[l];
            a1 += aw * vr[32 + l];
        }
        Ahp[h * DVV + l]      = a0;
        Ahp[h * DVV + 32 + l] = a1;
    }

    // A_v[w,v] = sum_h attn_v[h,w] * V[(h,w),v]   (warp owns w cols)
    for (int wc = w; wc < 64; wc += 8) {
        float a0 = 0.f, a1 = 0.f;
#pragma unroll 4
        for (int h = 0; h < 64; h++) {
            float avw = ss[h * 64 + wc];
            const float* vr = Vb + (size_t)(h * 64 + wc) * NKV;
            a0 += avw * vr[l];
            a1 += avw * vr[32 + l];
        }
        Avp[wc * DVV + l]      = a0;
        Avp[wc * DVV + 32 + l] = a1;
    }
}

// ---------------- 5) outer-product combine: A[b,h,w,v] = sum_n Ah*Av -------
__global__ __launch_bounds__(512) void combine_kernel() {
    int b = blockIdx.x >> 6, h = blockIdx.x & 63;
    int tid = threadIdx.x;
    __shared__ float sAh[NHEAD * DVV];  // 512 floats
    {
        int n = tid >> 6, v = tid & 63;
        sAh[tid] = g_Ah[((size_t)(b * NHEAD + n) * HH + h) * DVV + v];
    }
    __syncthreads();
    int v = tid & 63, wg = tid >> 6;
    for (int wc = wg; wc < 64; wc += 8) {
        float acc = 0.f;
#pragma unroll
        for (int n = 0; n < NHEAD; n++)
            acc += sAh[n * 64 + v] *
                   g_Av[((size_t)(b * NHEAD + n) * WWID + wc) * DVV + v];
        g_A[(((size_t)(b * HH + h)) * WWID + wc) * DVV + v] = acc;
    }
}

// ---------------- launch ----------------------------------------------------
extern "C" void kernel_launch(void* const* d_in, const int* in_sizes, int n_in,
                              void* d_out, int out_size) {
    const float* x  = (const float*)d_in[0];
    const float* Wq = (const float*)d_in[1];
    const float* bq = (const float*)d_in[2];
    const float* Wk = (const float*)d_in[3];
    const float* bk = (const float*)d_in[4];
    const float* Wv = (const float*)d_in[5];
    const float* bv = (const float*)d_in[6];
    const float* Wo = (const float*)d_in[7];
    const float* bo = (const float*)d_in[8];
    float* out = (float*)d_out;

    float *pK, *pV, *pA;
    cudaGetSymbolAddress((void**)&pK, g_K);
    cudaGetSymbolAddress((void**)&pV, g_V);
    cudaGetSymbolAddress((void**)&pA, g_A);

    pool_kernel<<<dim3(BSZ, 8), 512>>>(x);
    q_kernel<<<BSZ, 512>>>(Wq, bq);
    sgemm_bias<<<dim3(4, 512), 256>>>(MROWS, NKV, CDIM, x, Wk, bk, pK);
    sgemm_bias<<<dim3(4, 512), 256>>>(MROWS, NKV, CDIM, x, Wv, bv, pV);
    attn_kernel<<<BSZ * NHEAD, 256>>>();
    combine_kernel<<<BSZ * HH, 512>>>();
    sgemm_bias<<<dim3(4, 512), 256>>>(MROWS, 512, DVV, pA, Wo, bo, out);
}

// round 3
// speedup vs baseline: 4.5188x; 4.5188x over previous
#include <cuda_runtime.h>
#include <math.h>

// Problem dims
#define BSZ   16
#define HH    64
#define WWID  64
#define CDIM  512
#define NHEAD 8
#define DKK   64
#define DVV   64
#define PIX   4096
#define MROWS 65536

// ---------------- scratch (device globals; no runtime allocation) ----------
__device__ float g_partial[BSZ * 8 * CDIM];
__device__ float g_q[BSZ * NHEAD * DKK];              // [b][n*64+k]
__device__ float g_qW[BSZ * NHEAD * CDIM];            // [b][n][c], pre-scaled
__device__ float g_S[BSZ * NHEAD * PIX];              // scores [b][n][p]
__device__ float g_ah[BSZ * HH * NHEAD * WWID];       // attn_h [b][h][n][w]
__device__ float g_av[BSZ * WWID * NHEAD * HH];       // attn_v [b][w][n][h]
__device__ float g_yh[(size_t)NHEAD * BSZ * HH * CDIM];   // [n][b*64+h][c]
__device__ float g_yv[(size_t)NHEAD * BSZ * WWID * CDIM]; // [n][b*64+w][c]
__device__ float g_Ah[BSZ * NHEAD * HH * DVV];        // [b][n][h][v]
__device__ float g_Av[BSZ * NHEAD * WWID * DVV];      // [b][n][w][v]
__device__ float g_A[(size_t)MROWS * DVV];            // [b*4096+h*64+w][v]

// ---------------- 1) spatial mean pooling (partials) -----------------------
__global__ void pool_kernel(const float* __restrict__ x) {
    int b = blockIdx.x, j = blockIdx.y, c = threadIdx.x;
    const float* xp = x + ((size_t)b * PIX + (size_t)j * 512) * CDIM + c;
    float s = 0.f;
#pragma unroll 8
    for (int p = 0; p < 512; p++) s += xp[(size_t)p * CDIM];
    g_partial[(b * 8 + j) * CDIM + c] = s;
}

// ---------------- 2) q = pooled @ Wq + bq -----------------------------------
__global__ void q_kernel(const float* __restrict__ Wq, const float* __restrict__ bq) {
    int b = blockIdx.x, t = threadIdx.x;
    __shared__ float sp[CDIM];
    float s = 0.f;
#pragma unroll
    for (int j = 0; j < 8; j++) s += g_partial[(b * 8 + j) * CDIM + t];
    sp[t] = s * (1.0f / 4096.0f);
    __syncthreads();
    float acc = bq[t];
#pragma unroll 8
    for (int c = 0; c < CDIM; c++) acc += sp[c] * Wq[c * 512 + t];
    g_q[b * 512 + t] = acc;
}

// ---------------- 3) qW[b,n,c] = scale * sum_k Wk[c, n*64+k] q[b,n,k] ------
__global__ void qw_kernel(const float* __restrict__ Wk) {
    int b = blockIdx.x, n = blockIdx.y, c = threadIdx.x;  // 512 threads
    __shared__ float sq[64];
    if (c < 64) sq[c] = g_q[b * 512 + n * 64 + c];
    __syncthreads();
    const float* wr = Wk + (size_t)c * 512 + n * 64;
    float acc = 0.f;
#pragma unroll
    for (int k = 0; k < 64; k++) acc += sq[k] * wr[k];
    g_qW[(b * 8 + n) * 512 + c] = acc * 0.125f;   // fold 1/sqrt(dk)
}

// ---------------- 4) scores: s[b,n,p] = x[b,p,:] . qW[b,n,:] ---------------
__global__ __launch_bounds__(128) void score_kernel(const float* __restrict__ x) {
    int b = blockIdx.x;
    int p = blockIdx.y * 128 + threadIdx.x;
    __shared__ float4 sqw[8][128];
    for (int i = threadIdx.x; i < 1024; i += 128) {
        int n = i >> 7, c4 = i & 127;
        sqw[n][c4] = ((const float4*)(g_qW + (size_t)(b * 8 + n) * 512))[c4];
    }
    __syncthreads();
    const float4* xr = (const float4*)(x + ((size_t)b * PIX + p) * CDIM);
    float acc[8] = {0.f, 0.f, 0.f, 0.f, 0.f, 0.f, 0.f, 0.f};
#pragma unroll 4
    for (int c4 = 0; c4 < 128; c4++) {
        float4 xv = xr[c4];
#pragma unroll
        for (int n = 0; n < 8; n++) {
            float4 w = sqw[n][c4];
            acc[n] += xv.x * w.x + xv.y * w.y + xv.z * w.z + xv.w * w.w;
        }
    }
#pragma unroll
    for (int n = 0; n < 8; n++)
        g_S[(size_t)(b * 8 + n) * PIX + p] = acc[n];
}

// ---------------- 5) dual softmax per (b,n), write transposed layouts ------
__global__ __launch_bounds__(256) void softmax_kernel() {
    int bn = blockIdx.x;
    int b = bn >> 3, n = bn & 7;
    int tid = threadIdx.x, w = tid >> 5, l = tid & 31;
    __shared__ float ss[4096];
    for (int i = tid; i < 4096; i += 256) ss[i] = g_S[(size_t)bn * 4096 + i];
    __syncthreads();

    // row softmax over w -> attn_h [b][h][n][w]
    for (int h = w; h < 64; h += 8) {
        float x0 = ss[h * 64 + l], x1 = ss[h * 64 + 32 + l];
        float m = fmaxf(x0, x1);
#pragma unroll
        for (int o = 16; o > 0; o >>= 1)
            m = fmaxf(m, __shfl_xor_sync(0xffffffffu, m, o));
        float e0 = __expf(x0 - m), e1 = __expf(x1 - m);
        float sum = e0 + e1;
#pragma unroll
        for (int o = 16; o > 0; o >>= 1)
            sum += __shfl_xor_sync(0xffffffffu, sum, o);
        float inv = 1.0f / sum;
        float* dst = g_ah + ((size_t)(b * 64 + h) * 8 + n) * 64;
        dst[l] = e0 * inv;
        dst[32 + l] = e1 * inv;
    }

    // column softmax over h -> attn_v [b][w][n][h]
    if (tid < 64) {
        int c = tid;
        float m = -1e30f;
#pragma unroll 8
        for (int h = 0; h < 64; h++) m = fmaxf(m, ss[h * 64 + c]);
        float sum = 0.f;
#pragma unroll 8
        for (int h = 0; h < 64; h++) sum += __expf(ss[h * 64 + c] - m);
        float inv = 1.0f / sum;
        float* dst = g_av + ((size_t)(b * 64 + c) * 8 + n) * 64;
#pragma unroll 8
        for (int h = 0; h < 64; h++)
            dst[h] = __expf(ss[h * 64 + c] - m) * inv;
    }
}

// ---------------- 6) y_h / y_v: weighted sums of x rows --------------------
// path 0: block (b, h): y_h[n, b*64+h, c] = sum_w attn_h[n,w] * x[b,h,w,c]
// path 1: block (b, w): y_v[n, b*64+w, c] = sum_h attn_v[n,h] * x[b,h,w,c]
__global__ __launch_bounds__(128) void y_kernel(const float* __restrict__ x) {
    int b = blockIdx.x, s = blockIdx.y, path = blockIdx.z;
    int tid = threadIdx.x;
    __shared__ float sa[512];
    const float* asrc = (path ? g_av : g_ah) + (size_t)(b * 64 + s) * 512;
    for (int i = tid; i < 512; i += 128) sa[i] = asrc[i];
    __syncthreads();

    size_t base = (size_t)b * PIX * CDIM +
                  (path ? (size_t)s * CDIM : (size_t)s * 64 * CDIM);
    size_t stride4 = (path ? (size_t)64 * CDIM : (size_t)CDIM) / 4;
    const float4* xp = (const float4*)(x) + base / 4 + tid;

    float4 acc[8];
#pragma unroll
    for (int n = 0; n < 8; n++) acc[n] = make_float4(0.f, 0.f, 0.f, 0.f);

#pragma unroll 4
    for (int j = 0; j < 64; j++) {
        float4 xv = xp[j * stride4];
#pragma unroll
        for (int n = 0; n < 8; n++) {
            float f = sa[n * 64 + j];
            acc[n].x += f * xv.x;
            acc[n].y += f * xv.y;
            acc[n].z += f * xv.z;
            acc[n].w += f * xv.w;
        }
    }
    float* yout = path ? g_yv : g_yh;
#pragma unroll
    for (int n = 0; n < 8; n++)
        ((float4*)(yout + ((size_t)(n * 1024 + b * 64 + s)) * 512))[tid] = acc[n];
}

// ---------------- 7) project y -> A_h / A_v (per-head 64-col GEMM) ---------
// block (n, b, path): out[b,n, 64x64] = Y_n[b*64.., 512] @ Wv[:, n*64..] + bv
__global__ __launch_bounds__(256) void aproj_kernel(
    const float* __restrict__ Wv, const float* __restrict__ bv)
{
    int n = blockIdx.x, b = blockIdx.y, path = blockIdx.z;
    const float* Y = (path ? g_yv : g_yh) + ((size_t)(n * 1024 + b * 64)) * 512;
    float* outp = (path ? g_Av : g_Ah) + (size_t)(b * 8 + n) * 4096;
    __shared__ float sY[64][32];
    __shared__ float sW[32][64];
    int tid = threadIdx.x;
    int tr = tid >> 4, tc = tid & 15;
    float acc[4][4];
#pragma unroll
    for (int i = 0; i < 4; i++)
#pragma unroll
        for (int j = 0; j < 4; j++) acc[i][j] = 0.f;

    for (int k0 = 0; k0 < 512; k0 += 32) {
        for (int i = tid; i < 512; i += 256) {
            int r = i >> 3, c4 = i & 7;
            *(float4*)&sY[r][c4 * 4] =
                *(const float4*)(Y + (size_t)r * 512 + k0 + c4 * 4);
        }
        for (int i = tid; i < 512; i += 256) {
            int r = i >> 4, c4 = i & 15;
            *(float4*)&sW[r][c4 * 4] =
                *(const float4*)(Wv + (size_t)(k0 + r) * 512 + n * 64 + c4 * 4);
        }
        __syncthreads();
#pragma unroll
        for (int k = 0; k < 32; k++) {
            float4 bw = *(float4*)&sW[k][tc * 4];
            float a0 = sY[tr * 4 + 0][k], a1 = sY[tr * 4 + 1][k];
            float a2 = sY[tr * 4 + 2][k], a3 = sY[tr * 4 + 3][k];
            acc[0][0] += a0 * bw.x; acc[0][1] += a0 * bw.y; acc[0][2] += a0 * bw.z; acc[0][3] += a0 * bw.w;
            acc[1][0] += a1 * bw.x; acc[1][1] += a1 * bw.y; acc[1][2] += a1 * bw.z; acc[1][3] += a1 * bw.w;
            acc[2][0] += a2 * bw.x; acc[2][1] += a2 * bw.y; acc[2][2] += a2 * bw.z; acc[2][3] += a2 * bw.w;
            acc[3][0] += a3 * bw.x; acc[3][1] += a3 * bw.y; acc[3][2] += a3 * bw.z; acc[3][3] += a3 * bw.w;
        }
        __syncthreads();
    }
    float bb[4];
#pragma unroll
    for (int j = 0; j < 4; j++) bb[j] = bv[n * 64 + tc * 4 + j];
#pragma unroll
    for (int i = 0; i < 4; i++)
#pragma unroll
        for (int j = 0; j < 4; j++)
            outp[(tr * 4 + i) * 64 + tc * 4 + j] = acc[i][j] + bb[j];
}

// ---------------- 8) combine: A[b,h,w,v] = sum_n Ah[b,n,h,v]*Av[b,n,w,v] ---
__global__ __launch_bounds__(512) void combine_kernel() {
    int b = blockIdx.x >> 6, h = blockIdx.x & 63;
    int tid = threadIdx.x;
    __shared__ float sAh[NHEAD * DVV];
    {
        int n = tid >> 6, v = tid & 63;
        sAh[tid] = g_Ah[((size_t)(b * 8 + n) * 64 + h) * 64 + v];
    }
    __syncthreads();
    int v = tid & 63, wg = tid >> 6;
    for (int wc = wg; wc < 64; wc += 8) {
        float acc = 0.f;
#pragma unroll
        for (int n = 0; n < NHEAD; n++)
            acc += sAh[n * 64 + v] *
                   g_Av[((size_t)(b * 8 + n) * 64 + wc) * 64 + v];
        g_A[(((size_t)(b * 64 + h)) * 64 + wc) * 64 + v] = acc;
    }
}

// ---------------- 9) fp32 SGEMM (proven) for output projection -------------
__global__ __launch_bounds__(256) void sgemm_bias(
    int M, int N, int Kd,
    const float* __restrict__ A, const float* __restrict__ Bm,
    const float* __restrict__ bias, float* __restrict__ Cm)
{
    const int BM = 128, BN = 128, BK = 8, TM = 8, TN = 8;
    __shared__ float As[BK][BM];
    __shared__ float Bs[BK][BN];
    int tid = threadIdx.x;
    int bx = blockIdx.x, by = blockIdx.y;
    int tcol = tid & 15;
    int trow = tid >> 4;
    int aRow = tid >> 1, aCol = (tid & 1) * 4;
    int bRow = tid >> 5, bCol = (tid & 31) * 4;

    const float* Ag = A + (size_t)by * BM * Kd;
    const float* Bg = Bm + (size_t)bx * BN;

    float acc[TM][TN];
#pragma unroll
    for (int i = 0; i < TM; i++)
#pragma unroll
        for (int j = 0; j < TN; j++) acc[i][j] = 0.f;

    for (int k0 = 0; k0 < Kd; k0 += BK) {
        float4 av = *(const float4*)(Ag + (size_t)aRow * Kd + k0 + aCol);
        As[aCol + 0][aRow] = av.x;
        As[aCol + 1][aRow] = av.y;
        As[aCol + 2][aRow] = av.z;
        As[aCol + 3][aRow] = av.w;
        *(float4*)(&Bs[bRow][bCol]) =
            *(const float4*)(Bg + (size_t)(k0 + bRow) * N + bCol);
        __syncthreads();
#pragma unroll
        for (int k = 0; k < BK; k++) {
            float4 a0 = *(const float4*)(&As[k][trow * TM]);
            float4 a1 = *(const float4*)(&As[k][trow * TM + 4]);
            float4 b0 = *(const float4*)(&Bs[k][tcol * TN]);
            float4 b1 = *(const float4*)(&Bs[k][tcol * TN + 4]);
            float ar[8] = {a0.x, a0.y, a0.z, a0.w, a1.x, a1.y, a1.z, a1.w};
            float br[8] = {b0.x, b0.y, b0.z, b0.w, b1.x, b1.y, b1.z, b1.w};
#pragma unroll
            for (int i = 0; i < TM; i++)
#pragma unroll
                for (int j = 0; j < TN; j++) acc[i][j] += ar[i] * br[j];
        }
        __syncthreads();
    }

    int colBase = bx * BN + tcol * TN;
    float bb[TN];
#pragma unroll
    for (int j = 0; j < TN; j++) bb[j] = bias[colBase + j];
#pragma unroll
    for (int i = 0; i < TM; i++) {
        size_t row = (size_t)by * BM + trow * TM + i;
        float4 o0 = {acc[i][0] + bb[0], acc[i][1] + bb[1],
                     acc[i][2] + bb[2], acc[i][3] + bb[3]};
        float4 o1 = {acc[i][4] + bb[4], acc[i][5] + bb[5],
                     acc[i][6] + bb[6], acc[i][7] + bb[7]};
        *(float4*)(Cm + row * N + colBase)     = o0;
        *(float4*)(Cm + row * N + colBase + 4) = o1;
    }
}

// ---------------- launch ----------------------------------------------------
extern "C" void kernel_launch(void* const* d_in, const int* in_sizes, int n_in,
                              void* d_out, int out_size) {
    const float* x  = (const float*)d_in[0];
    const float* Wq = (const float*)d_in[1];
    const float* bq = (const float*)d_in[2];
    const float* Wk = (const float*)d_in[3];
    const float* bk = (const float*)d_in[4];  (void)bk;  // cancels in softmax
    const float* Wv = (const float*)d_in[5];
    const float* bv = (const float*)d_in[6];
    const float* Wo = (const float*)d_in[7];
    const float* bo = (const float*)d_in[8];
    float* out = (float*)d_out;

    float* pA;
    cudaGetSymbolAddress((void**)&pA, g_A);

    pool_kernel<<<dim3(BSZ, 8), 512>>>(x);
    q_kernel<<<BSZ, 512>>>(Wq, bq);
    qw_kernel<<<dim3(BSZ, NHEAD), 512>>>(Wk);
    score_kernel<<<dim3(BSZ, 32), 128>>>(x);
    softmax_kernel<<<BSZ * NHEAD, 256>>>();
    y_kernel<<<dim3(BSZ, 64, 2), 128>>>(x);
    aproj_kernel<<<dim3(NHEAD, BSZ, 2), 256>>>(Wv, bv);
    combine_kernel<<<BSZ * HH, 512>>>();
    sgemm_bias<<<dim3(4, 512), 256>>>(MROWS, 512, DVV, pA, Wo, bo, out);
}

// round 4
// speedup vs baseline: 5.0136x; 1.1095x over previous
#include <cuda_runtime.h>
#include <math.h>

// Problem dims
#define BSZ   16
#define HH    64
#define WWID  64
#define CDIM  512
#define NHEAD 8
#define DKK   64
#define DVV   64
#define PIX   4096
#define MROWS 65536

// ---------------- scratch (device globals; no runtime allocation) ----------
__device__ float g_partial[BSZ * 32 * CDIM];
__device__ float g_q[BSZ * NHEAD * DKK];              // [b][n*64+k]
__device__ float g_qW[BSZ * NHEAD * CDIM];            // [b][n][c], pre-scaled
__device__ float g_S[BSZ * NHEAD * PIX];              // scores [b][n][p]
__device__ float g_ah[BSZ * HH * NHEAD * WWID];       // attn_h [b][h][n][w]
__device__ float g_av[BSZ * WWID * NHEAD * HH];       // attn_v [b][w][n][h]
__device__ float g_yh[(size_t)NHEAD * BSZ * HH * CDIM];   // [n][b*64+h][c]
__device__ float g_yv[(size_t)NHEAD * BSZ * WWID * CDIM]; // [n][b*64+w][c]
__device__ float g_Ah[BSZ * NHEAD * HH * DVV];        // [b][n][h][v]
__device__ float g_Av[BSZ * NHEAD * WWID * DVV];      // [b][n][w][v]
__device__ float g_A[(size_t)MROWS * DVV];            // [b*4096+h*64+w][v]

// ---------------- 1) spatial mean pooling (finer grid) ---------------------
__global__ __launch_bounds__(512) void pool_kernel(const float* __restrict__ x) {
    int b = blockIdx.x, j = blockIdx.y, c = threadIdx.x;
    const float* xp = x + ((size_t)b * PIX + (size_t)j * 128) * CDIM + c;
    float s = 0.f;
#pragma unroll 8
    for (int p = 0; p < 128; p++) s += xp[(size_t)p * CDIM];
    g_partial[(b * 32 + j) * CDIM + c] = s;
}

// ---------------- 2) q = pooled @ Wq + bq -----------------------------------
__global__ void q_kernel(const float* __restrict__ Wq, const float* __restrict__ bq) {
    int b = blockIdx.x, t = threadIdx.x;
    __shared__ float sp[CDIM];
    float s = 0.f;
#pragma unroll
    for (int j = 0; j < 32; j++) s += g_partial[(b * 32 + j) * CDIM + t];
    sp[t] = s * (1.0f / 4096.0f);
    __syncthreads();
    float acc = bq[t];
#pragma unroll 8
    for (int c = 0; c < CDIM; c++) acc += sp[c] * Wq[c * 512 + t];
    g_q[b * 512 + t] = acc;
}

// ---------------- 3) qW[b,n,c] = scale * sum_k Wk[c, n*64+k] q[b,n,k] ------
__global__ void qw_kernel(const float* __restrict__ Wk) {
    int b = blockIdx.x, n = blockIdx.y, c = threadIdx.x;  // 512 threads
    __shared__ float sq[64];
    if (c < 64) sq[c] = g_q[b * 512 + n * 64 + c];
    __syncthreads();
    const float* wr = Wk + (size_t)c * 512 + n * 64;
    float acc = 0.f;
#pragma unroll
    for (int k = 0; k < 64; k++) acc += sq[k] * wr[k];
    g_qW[(b * 8 + n) * 512 + c] = acc * 0.125f;   // fold 1/sqrt(dk)
}

// ---------------- 4) scores, warp-cooperative & coalesced ------------------
// block: 256 thr = 8 warps, 32 pixels. warp handles 4 pixels; per pixel the
// warp does a coalesced 512-wide dot against 8 heads, then shfl-reduces.
__global__ __launch_bounds__(256) void score_kernel(const float* __restrict__ x) {
    int b = blockIdx.x;
    int p0 = blockIdx.y * 32;
    int tid = threadIdx.x, warp = tid >> 5, lane = tid & 31;

    __shared__ float4 sqw[8][128];   // qW for all heads, 16KB
    for (int i = tid; i < 1024; i += 256) {
        int n = i >> 7, c4 = i & 127;
        sqw[n][c4] = ((const float4*)(g_qW + (size_t)(b * 8 + n) * 512))[c4];
    }
    __syncthreads();

#pragma unroll
    for (int pi = 0; pi < 4; pi++) {
        int p = p0 + warp * 4 + pi;
        const float4* xr = (const float4*)(x + ((size_t)b * PIX + p) * CDIM) + lane;
        float4 xv[4];
#pragma unroll
        for (int j = 0; j < 4; j++) xv[j] = xr[j * 32];   // coalesced, MLP=4
        float acc[8] = {0.f, 0.f, 0.f, 0.f, 0.f, 0.f, 0.f, 0.f};
#pragma unroll
        for (int j = 0; j < 4; j++) {
#pragma unroll
            for (int n = 0; n < 8; n++) {
                float4 w = sqw[n][lane + j * 32];
                acc[n] += xv[j].x * w.x + xv[j].y * w.y +
                          xv[j].z * w.z + xv[j].w * w.w;
            }
        }
#pragma unroll
        for (int n = 0; n < 8; n++) {
#pragma unroll
            for (int o = 16; o > 0; o >>= 1)
                acc[n] += __shfl_xor_sync(0xffffffffu, acc[n], o);
        }
        if (lane < 8)
            g_S[(size_t)(b * 8 + lane) * PIX + p] = acc[lane];  // lane n holds full sum
    }
}

// ---------------- 5) dual softmax per (b,n), write transposed layouts ------
__global__ __launch_bounds__(256) void softmax_kernel() {
    int bn = blockIdx.x;
    int b = bn >> 3, n = bn & 7;
    int tid = threadIdx.x, w = tid >> 5, l = tid & 31;
    __shared__ float ss[4096];
    for (int i = tid; i < 4096; i += 256) ss[i] = g_S[(size_t)bn * 4096 + i];
    __syncthreads();

    for (int h = w; h < 64; h += 8) {
        float x0 = ss[h * 64 + l], x1 = ss[h * 64 + 32 + l];
        float m = fmaxf(x0, x1);
#pragma unroll
        for (int o = 16; o > 0; o >>= 1)
            m = fmaxf(m, __shfl_xor_sync(0xffffffffu, m, o));
        float e0 = __expf(x0 - m), e1 = __expf(x1 - m);
        float sum = e0 + e1;
#pragma unroll
        for (int o = 16; o > 0; o >>= 1)
            sum += __shfl_xor_sync(0xffffffffu, sum, o);
        float inv = 1.0f / sum;
        float* dst = g_ah + ((size_t)(b * 64 + h) * 8 + n) * 64;
        dst[l] = e0 * inv;
        dst[32 + l] = e1 * inv;
    }

    if (tid < 64) {
        int c = tid;
        float m = -1e30f;
#pragma unroll 8
        for (int h = 0; h < 64; h++) m = fmaxf(m, ss[h * 64 + c]);
        float sum = 0.f;
#pragma unroll 8
        for (int h = 0; h < 64; h++) sum += __expf(ss[h * 64 + c] - m);
        float inv = 1.0f / sum;
        float* dst = g_av + ((size_t)(b * 64 + c) * 8 + n) * 64;
#pragma unroll 8
        for (int h = 0; h < 64; h++)
            dst[h] = __expf(ss[h * 64 + c] - m) * inv;
    }
}

// ---------------- 6) y_h / y_v: weighted sums of x rows --------------------
__global__ __launch_bounds__(128) void y_kernel(const float* __restrict__ x) {
    int b = blockIdx.x, s = blockIdx.y, path = blockIdx.z;
    int tid = threadIdx.x;
    __shared__ float sa[512];
    const float* asrc = (path ? g_av : g_ah) + (size_t)(b * 64 + s) * 512;
    for (int i = tid; i < 512; i += 128) sa[i] = asrc[i];
    __syncthreads();

    size_t base = (size_t)b * PIX * CDIM +
                  (path ? (size_t)s * CDIM : (size_t)s * 64 * CDIM);
    size_t stride4 = (path ? (size_t)64 * CDIM : (size_t)CDIM) / 4;
    const float4* xp = (const float4*)(x) + base / 4 + tid;

    float4 acc[8];
#pragma unroll
    for (int n = 0; n < 8; n++) acc[n] = make_float4(0.f, 0.f, 0.f, 0.f);

#pragma unroll 8
    for (int j = 0; j < 64; j++) {
        float4 xv = xp[j * stride4];
#pragma unroll
        for (int n = 0; n < 8; n++) {
            float f = sa[n * 64 + j];
            acc[n].x += f * xv.x;
            acc[n].y += f * xv.y;
            acc[n].z += f * xv.z;
            acc[n].w += f * xv.w;
        }
    }
    float* yout = path ? g_yv : g_yh;
#pragma unroll
    for (int n = 0; n < 8; n++)
        ((float4*)(yout + ((size_t)(n * 1024 + b * 64 + s)) * 512))[tid] = acc[n];
}

// ---------------- 7) project y -> A_h / A_v (per-head 64-col GEMM) ---------
__global__ __launch_bounds__(256) void aproj_kernel(
    const float* __restrict__ Wv, const float* __restrict__ bv)
{
    int n = blockIdx.x, b = blockIdx.y, path = blockIdx.z;
    const float* Y = (path ? g_yv : g_yh) + ((size_t)(n * 1024 + b * 64)) * 512;
    float* outp = (path ? g_Av : g_Ah) + (size_t)(b * 8 + n) * 4096;
    __shared__ float sY[64][32];
    __shared__ float sW[32][64];
    int tid = threadIdx.x;
    int tr = tid >> 4, tc = tid & 15;
    float acc[4][4];
#pragma unroll
    for (int i = 0; i < 4; i++)
#pragma unroll
        for (int j = 0; j < 4; j++) acc[i][j] = 0.f;

    for (int k0 = 0; k0 < 512; k0 += 32) {
        for (int i = tid; i < 512; i += 256) {
            int r = i >> 3, c4 = i & 7;
            *(float4*)&sY[r][c4 * 4] =
                *(const float4*)(Y + (size_t)r * 512 + k0 + c4 * 4);
        }
        for (int i = tid; i < 512; i += 256) {
            int r = i >> 4, c4 = i & 15;
            *(float4*)&sW[r][c4 * 4] =
                *(const float4*)(Wv + (size_t)(k0 + r) * 512 + n * 64 + c4 * 4);
        }
        __syncthreads();
#pragma unroll
        for (int k = 0; k < 32; k++) {
            float4 bw = *(float4*)&sW[k][tc * 4];
            float a0 = sY[tr * 4 + 0][k], a1 = sY[tr * 4 + 1][k];
            float a2 = sY[tr * 4 + 2][k], a3 = sY[tr * 4 + 3][k];
            acc[0][0] += a0 * bw.x; acc[0][1] += a0 * bw.y; acc[0][2] += a0 * bw.z; acc[0][3] += a0 * bw.w;
            acc[1][0] += a1 * bw.x; acc[1][1] += a1 * bw.y; acc[1][2] += a1 * bw.z; acc[1][3] += a1 * bw.w;
            acc[2][0] += a2 * bw.x; acc[2][1] += a2 * bw.y; acc[2][2] += a2 * bw.z; acc[2][3] += a2 * bw.w;
            acc[3][0] += a3 * bw.x; acc[3][1] += a3 * bw.y; acc[3][2] += a3 * bw.z; acc[3][3] += a3 * bw.w;
        }
        __syncthreads();
    }
    float bb[4];
#pragma unroll
    for (int j = 0; j < 4; j++) bb[j] = bv[n * 64 + tc * 4 + j];
#pragma unroll
    for (int i = 0; i < 4; i++)
#pragma unroll
        for (int j = 0; j < 4; j++)
            outp[(tr * 4 + i) * 64 + tc * 4 + j] = acc[i][j] + bb[j];
}

// ---------------- 8) combine: A[b,h,w,v] = sum_n Ah[b,n,h,v]*Av[b,n,w,v] ---
__global__ __launch_bounds__(512) void combine_kernel() {
    int b = blockIdx.x >> 6, h = blockIdx.x & 63;
    int tid = threadIdx.x;
    __shared__ float sAh[NHEAD * DVV];
    {
        int n = tid >> 6, v = tid & 63;
        sAh[tid] = g_Ah[((size_t)(b * 8 + n) * 64 + h) * 64 + v];
    }
    __syncthreads();
    int v = tid & 63, wg = tid >> 6;
    for (int wc = wg; wc < 64; wc += 8) {
        float acc = 0.f;
#pragma unroll
        for (int n = 0; n < NHEAD; n++)
            acc += sAh[n * 64 + v] *
                   g_Av[((size_t)(b * 8 + n) * 64 + wc) * 64 + v];
        g_A[(((size_t)(b * 64 + h)) * 64 + wc) * 64 + v] = acc;
    }
}

// ---------------- 9) fp32 SGEMM for output projection -----------------------
__global__ __launch_bounds__(256) void sgemm_bias(
    int M, int N, int Kd,
    const float* __restrict__ A, const float* __restrict__ Bm,
    const float* __restrict__ bias, float* __restrict__ Cm)
{
    const int BM = 128, BN = 128, BK = 8, TM = 8, TN = 8;
    __shared__ float As[BK][BM];
    __shared__ float Bs[BK][BN];
    int tid = threadIdx.x;
    int bx = blockIdx.x, by = blockIdx.y;
    int tcol = tid & 15;
    int trow = tid >> 4;
    int aRow = tid >> 1, aCol = (tid & 1) * 4;
    int bRow = tid >> 5, bCol = (tid & 31) * 4;

    const float* Ag = A + (size_t)by * BM * Kd;
    const float* Bg = Bm + (size_t)bx * BN;

    float acc[TM][TN];
#pragma unroll
    for (int i = 0; i < TM; i++)
#pragma unroll
        for (int j = 0; j < TN; j++) acc[i][j] = 0.f;

    for (int k0 = 0; k0 < Kd; k0 += BK) {
        float4 av = *(const float4*)(Ag + (size_t)aRow * Kd + k0 + aCol);
        As[aCol + 0][aRow] = av.x;
        As[aCol + 1][aRow] = av.y;
        As[aCol + 2][aRow] = av.z;
        As[aCol + 3][aRow] = av.w;
        *(float4*)(&Bs[bRow][bCol]) =
            *(const float4*)(Bg + (size_t)(k0 + bRow) * N + bCol);
        __syncthreads();
#pragma unroll
        for (int k = 0; k < BK; k++) {
            float4 a0 = *(const float4*)(&As[k][trow * TM]);
            float4 a1 = *(const float4*)(&As[k][trow * TM + 4]);
            float4 b0 = *(const float4*)(&Bs[k][tcol * TN]);
            float4 b1 = *(const float4*)(&Bs[k][tcol * TN + 4]);
            float ar[8] = {a0.x, a0.y, a0.z, a0.w, a1.x, a1.y, a1.z, a1.w};
            float br[8] = {b0.x, b0.y, b0.z, b0.w, b1.x, b1.y, b1.z, b1.w};
#pragma unroll
            for (int i = 0; i < TM; i++)
#pragma unroll
                for (int j = 0; j < TN; j++) acc[i][j] += ar[i] * br[j];
        }
        __syncthreads();
    }

    int colBase = bx * BN + tcol * TN;
    float bb[TN];
#pragma unroll
    for (int j = 0; j < TN; j++) bb[j] = bias[colBase + j];
#pragma unroll
    for (int i = 0; i < TM; i++) {
        size_t row = (size_t)by * BM + trow * TM + i;
        float4 o0 = {acc[i][0] + bb[0], acc[i][1] + bb[1],
                     acc[i][2] + bb[2], acc[i][3] + bb[3]};
        float4 o1 = {acc[i][4] + bb[4], acc[i][5] + bb[5],
                     acc[i][6] + bb[6], acc[i][7] + bb[7]};
        *(float4*)(Cm + row * N + colBase)     = o0;
        *(float4*)(Cm + row * N + colBase + 4) = o1;
    }
}

// ---------------- launch ----------------------------------------------------
extern "C" void kernel_launch(void* const* d_in, const int* in_sizes, int n_in,
                              void* d_out, int out_size) {
    const float* x  = (const float*)d_in[0];
    const float* Wq = (const float*)d_in[1];
    const float* bq = (const float*)d_in[2];
    const float* Wk = (const float*)d_in[3];
    const float* bk = (const float*)d_in[4];  (void)bk;  // cancels in softmax
    const float* Wv = (const float*)d_in[5];
    const float* bv = (const float*)d_in[6];
    const float* Wo = (const float*)d_in[7];
    const float* bo = (const float*)d_in[8];
    float* out = (float*)d_out;

    float* pA;
    cudaGetSymbolAddress((void**)&pA, g_A);

    pool_kernel<<<dim3(BSZ, 32), 512>>>(x);
    q_kernel<<<BSZ, 512>>>(Wq, bq);
    qw_kernel<<<dim3(BSZ, NHEAD), 512>>>(Wk);
    score_kernel<<<dim3(BSZ, 128), 256>>>(x);
    softmax_kernel<<<BSZ * NHEAD, 256>>>();
    y_kernel<<<dim3(BSZ, 64, 2), 128>>>(x);
    aproj_kernel<<<dim3(NHEAD, BSZ, 2), 256>>>(Wv, bv);
    combine_kernel<<<BSZ * HH, 512>>>();
    sgemm_bias<<<dim3(4, 512), 256>>>(MROWS, 512, DVV, pA, Wo, bo, out);
}

// round 5
// speedup vs baseline: 5.1431x; 1.0258x over previous
#include <cuda_runtime.h>
#include <math.h>

// Problem dims
#define BSZ   16
#define HH    64
#define WWID  64
#define CDIM  512
#define NHEAD 8
#define DKK   64
#define DVV   64
#define PIX   4096
#define MROWS 65536

// ---------------- scratch (device globals; no runtime allocation) ----------
__device__ float g_partial[BSZ * 32 * CDIM];
__device__ float g_q[BSZ * NHEAD * DKK];              // [b][n*64+k]
__device__ float g_qW[BSZ * NHEAD * CDIM];            // [b][n][c], pre-scaled
__device__ float g_S[BSZ * NHEAD * PIX];              // scores [b][n][p]
__device__ float g_ah[BSZ * HH * NHEAD * WWID];       // attn_h [b][h][n][w]
__device__ float g_av[BSZ * WWID * NHEAD * HH];       // attn_v [b][w][n][h]
__device__ float g_yh[(size_t)NHEAD * BSZ * HH * CDIM];   // [n][b*64+h][c]
__device__ float g_yv[(size_t)NHEAD * BSZ * WWID * CDIM]; // [n][b*64+w][c]
__device__ float g_Ah[BSZ * NHEAD * HH * DVV];        // [b][n][h][v]
__device__ float g_Av[BSZ * NHEAD * WWID * DVV];      // [b][n][w][v]
__device__ float g_A[(size_t)MROWS * DVV];            // [b*4096+h*64+w][v]

// ---------------- 1) spatial mean pooling ----------------------------------
__global__ __launch_bounds__(512) void pool_kernel(const float* __restrict__ x) {
    int b = blockIdx.x, j = blockIdx.y, c = threadIdx.x;
    const float* xp = x + ((size_t)b * PIX + (size_t)j * 128) * CDIM + c;
    float s = 0.f;
#pragma unroll 8
    for (int p = 0; p < 128; p++) s += xp[(size_t)p * CDIM];
    g_partial[(b * 32 + j) * CDIM + c] = s;
}

// ---------------- 2) q = pooled @ Wq + bq -----------------------------------
__global__ void q_kernel(const float* __restrict__ Wq, const float* __restrict__ bq) {
    int b = blockIdx.x, t = threadIdx.x;
    __shared__ float sp[CDIM];
    float s = 0.f;
#pragma unroll
    for (int j = 0; j < 32; j++) s += g_partial[(b * 32 + j) * CDIM + t];
    sp[t] = s * (1.0f / 4096.0f);
    __syncthreads();
    float acc = bq[t];
#pragma unroll 8
    for (int c = 0; c < CDIM; c++) acc += sp[c] * Wq[c * 512 + t];
    g_q[b * 512 + t] = acc;
}

// ---------------- 3) qW[b,n,c] = scale * sum_k Wk[c, n*64+k] q[b,n,k] ------
__global__ void qw_kernel(const float* __restrict__ Wk) {
    int b = blockIdx.x, n = blockIdx.y, c = threadIdx.x;  // 512 threads
    __shared__ float sq[64];
    if (c < 64) sq[c] = g_q[b * 512 + n * 64 + c];
    __syncthreads();
    const float* wr = Wk + (size_t)c * 512 + n * 64;
    float acc = 0.f;
#pragma unroll
    for (int k = 0; k < 64; k++) acc += sq[k] * wr[k];
    g_qW[(b * 8 + n) * 512 + c] = acc * 0.125f;   // fold 1/sqrt(dk)
}

// ---------------- 4) scores, warp-per-pixel, low-reg / high-occ ------------
// 256 thr = 8 warps; warp handles 16 pixels SEQUENTIALLY (unroll 1 keeps regs low).
__global__ __launch_bounds__(256) void score_kernel(const float* __restrict__ x) {
    int b = blockIdx.x;
    int tid = threadIdx.x, warp = tid >> 5, lane = tid & 31;
    int pBase = blockIdx.y * 128 + warp * 16;

    __shared__ float4 sqw[8][128];   // qW for all heads, 16KB
    for (int i = tid; i < 1024; i += 256) {
        int n = i >> 7, c4 = i & 127;
        sqw[n][c4] = ((const float4*)(g_qW + (size_t)(b * 8 + n) * 512))[c4];
    }
    __syncthreads();

#pragma unroll 1
    for (int pi = 0; pi < 16; pi++) {
        int p = pBase + pi;
        const float4* xr = (const float4*)(x + ((size_t)b * PIX + p) * CDIM) + lane;
        float4 xv0 = xr[0], xv1 = xr[32], xv2 = xr[64], xv3 = xr[96];
        float acc[8];
#pragma unroll
        for (int n = 0; n < 8; n++) {
            float4 w0 = sqw[n][lane];
            float4 w1 = sqw[n][lane + 32];
            float4 w2 = sqw[n][lane + 64];
            float4 w3 = sqw[n][lane + 96];
            acc[n] = xv0.x * w0.x + xv0.y * w0.y + xv0.z * w0.z + xv0.w * w0.w
                   + xv1.x * w1.x + xv1.y * w1.y + xv1.z * w1.z + xv1.w * w1.w
                   + xv2.x * w2.x + xv2.y * w2.y + xv2.z * w2.z + xv2.w * w2.w
                   + xv3.x * w3.x + xv3.y * w3.y + xv3.z * w3.z + xv3.w * w3.w;
        }
#pragma unroll
        for (int n = 0; n < 8; n++) {
#pragma unroll
            for (int o = 16; o > 0; o >>= 1)
                acc[n] += __shfl_xor_sync(0xffffffffu, acc[n], o);
        }
        if (lane < 8)
            g_S[(size_t)(b * 8 + lane) * PIX + p] = acc[lane];
    }
}

// ---------------- 5) dual softmax per (b,n), write transposed layouts ------
__global__ __launch_bounds__(256) void softmax_kernel() {
    int bn = blockIdx.x;
    int b = bn >> 3, n = bn & 7;
    int tid = threadIdx.x, w = tid >> 5, l = tid & 31;
    __shared__ float ss[4096];
    for (int i = tid; i < 4096; i += 256) ss[i] = g_S[(size_t)bn * 4096 + i];
    __syncthreads();

    for (int h = w; h < 64; h += 8) {
        float x0 = ss[h * 64 + l], x1 = ss[h * 64 + 32 + l];
        float m = fmaxf(x0, x1);
#pragma unroll
        for (int o = 16; o > 0; o >>= 1)
            m = fmaxf(m, __shfl_xor_sync(0xffffffffu, m, o));
        float e0 = __expf(x0 - m), e1 = __expf(x1 - m);
        float sum = e0 + e1;
#pragma unroll
        for (int o = 16; o > 0; o >>= 1)
            sum += __shfl_xor_sync(0xffffffffu, sum, o);
        float inv = 1.0f / sum;
        float* dst = g_ah + ((size_t)(b * 64 + h) * 8 + n) * 64;
        dst[l] = e0 * inv;
        dst[32 + l] = e1 * inv;
    }

    if (tid < 64) {
        int c = tid;
        float m = -1e30f;
#pragma unroll 8
        for (int h = 0; h < 64; h++) m = fmaxf(m, ss[h * 64 + c]);
        float sum = 0.f;
#pragma unroll 8
        for (int h = 0; h < 64; h++) sum += __expf(ss[h * 64 + c] - m);
        float inv = 1.0f / sum;
        float* dst = g_av + ((size_t)(b * 64 + c) * 8 + n) * 64;
#pragma unroll 8
        for (int h = 0; h < 64; h++)
            dst[h] = __expf(ss[h * 64 + c] - m) * inv;
    }
}

// ---------------- 6) y_h / y_v: weighted sums of x rows --------------------
__global__ __launch_bounds__(128) void y_kernel(const float* __restrict__ x) {
    int b = blockIdx.x, s = blockIdx.y, path = blockIdx.z;
    int tid = threadIdx.x;
    __shared__ float sa[512];
    const float* asrc = (path ? g_av : g_ah) + (size_t)(b * 64 + s) * 512;
    for (int i = tid; i < 512; i += 128) sa[i] = asrc[i];
    __syncthreads();

    size_t base = (size_t)b * PIX * CDIM +
                  (path ? (size_t)s * CDIM : (size_t)s * 64 * CDIM);
    size_t stride4 = (path ? (size_t)64 * CDIM : (size_t)CDIM) / 4;
    const float4* xp = (const float4*)(x) + base / 4 + tid;

    float4 acc[8];
#pragma unroll
    for (int n = 0; n < 8; n++) acc[n] = make_float4(0.f, 0.f, 0.f, 0.f);

#pragma unroll 8
    for (int j = 0; j < 64; j++) {
        float4 xv = xp[j * stride4];
#pragma unroll
        for (int n = 0; n < 8; n++) {
            float f = sa[n * 64 + j];
            acc[n].x += f * xv.x;
            acc[n].y += f * xv.y;
            acc[n].z += f * xv.z;
            acc[n].w += f * xv.w;
        }
    }
    float* yout = path ? g_yv : g_yh;
#pragma unroll
    for (int n = 0; n < 8; n++)
        ((float4*)(yout + ((size_t)(n * 1024 + b * 64 + s)) * 512))[tid] = acc[n];
}

// ---------------- 7) project y -> A_h / A_v (per-head 64-col GEMM) ---------
__global__ __launch_bounds__(256) void aproj_kernel(
    const float* __restrict__ Wv, const float* __restrict__ bv)
{
    int n = blockIdx.x, b = blockIdx.y, path = blockIdx.z;
    const float* Y = (path ? g_yv : g_yh) + ((size_t)(n * 1024 + b * 64)) * 512;
    float* outp = (path ? g_Av : g_Ah) + (size_t)(b * 8 + n) * 4096;
    __shared__ float sY[64][32];
    __shared__ float sW[32][64];
    int tid = threadIdx.x;
    int tr = tid >> 4, tc = tid & 15;
    float acc[4][4];
#pragma unroll
    for (int i = 0; i < 4; i++)
#pragma unroll
        for (int j = 0; j < 4; j++) acc[i][j] = 0.f;

    for (int k0 = 0; k0 < 512; k0 += 32) {
        for (int i = tid; i < 512; i += 256) {
            int r = i >> 3, c4 = i & 7;
            *(float4*)&sY[r][c4 * 4] =
                *(const float4*)(Y + (size_t)r * 512 + k0 + c4 * 4);
        }
        for (int i = tid; i < 512; i += 256) {
            int r = i >> 4, c4 = i & 15;
            *(float4*)&sW[r][c4 * 4] =
                *(const float4*)(Wv + (size_t)(k0 + r) * 512 + n * 64 + c4 * 4);
        }
        __syncthreads();
#pragma unroll
        for (int k = 0; k < 32; k++) {
            float4 bw = *(float4*)&sW[k][tc * 4];
            float a0 = sY[tr * 4 + 0][k], a1 = sY[tr * 4 + 1][k];
            float a2 = sY[tr * 4 + 2][k], a3 = sY[tr * 4 + 3][k];
            acc[0][0] += a0 * bw.x; acc[0][1] += a0 * bw.y; acc[0][2] += a0 * bw.z; acc[0][3] += a0 * bw.w;
            acc[1][0] += a1 * bw.x; acc[1][1] += a1 * bw.y; acc[1][2] += a1 * bw.z; acc[1][3] += a1 * bw.w;
            acc[2][0] += a2 * bw.x; acc[2][1] += a2 * bw.y; acc[2][2] += a2 * bw.z; acc[2][3] += a2 * bw.w;
            acc[3][0] += a3 * bw.x; acc[3][1] += a3 * bw.y; acc[3][2] += a3 * bw.z; acc[3][3] += a3 * bw.w;
        }
        __syncthreads();
    }
    float bb[4];
#pragma unroll
    for (int j = 0; j < 4; j++) bb[j] = bv[n * 64 + tc * 4 + j];
#pragma unroll
    for (int i = 0; i < 4; i++)
#pragma unroll
        for (int j = 0; j < 4; j++)
            outp[(tr * 4 + i) * 64 + tc * 4 + j] = acc[i][j] + bb[j];
}

// ---------------- 8) combine: A[b,h,w,v] = sum_n Ah[b,n,h,v]*Av[b,n,w,v] ---
__global__ __launch_bounds__(512) void combine_kernel() {
    int b = blockIdx.x >> 6, h = blockIdx.x & 63;
    int tid = threadIdx.x;
    __shared__ float sAh[NHEAD * DVV];
    {
        int n = tid >> 6, v = tid & 63;
        sAh[tid] = g_Ah[((size_t)(b * 8 + n) * 64 + h) * 64 + v];
    }
    __syncthreads();
    int v = tid & 63, wg = tid >> 6;
    for (int wc = wg; wc < 64; wc += 8) {
        float acc = 0.f;
#pragma unroll
        for (int n = 0; n < NHEAD; n++)
            acc += sAh[n * 64 + v] *
                   g_Av[((size_t)(b * 8 + n) * 64 + wc) * 64 + v];
        g_A[(((size_t)(b * 64 + h)) * 64 + wc) * 64 + v] = acc;
    }
}

// ---------------- 9) fp32 SGEMM, BK=16 (fewer barriers) --------------------
__global__ __launch_bounds__(256) void sgemm_bias(
    int M, int N, int Kd,
    const float* __restrict__ A, const float* __restrict__ Bm,
    const float* __restrict__ bias, float* __restrict__ Cm)
{
    const int BM = 128, BN = 128, BK = 16, TM = 8, TN = 8;
    __shared__ float As[BK][BM];
    __shared__ float Bs[BK][BN];
    int tid = threadIdx.x;
    int bx = blockIdx.x, by = blockIdx.y;
    int tcol = tid & 15;
    int trow = tid >> 4;
    // A tile 128x16: 512 float4, 2 per thread
    int aRow = tid >> 2, aCol = (tid & 3) * 4;        // rows 0..63 (+64 second)
    // B tile 16x128: 512 float4, 2 per thread
    int bRow = tid >> 5, bCol = (tid & 31) * 4;       // rows 0..7 (+8 second)

    const float* Ag = A + (size_t)by * BM * Kd;
    const float* Bg = Bm + (size_t)bx * BN;

    float acc[TM][TN];
#pragma unroll
    for (int i = 0; i < TM; i++)
#pragma unroll
        for (int j = 0; j < TN; j++) acc[i][j] = 0.f;

    for (int k0 = 0; k0 < Kd; k0 += BK) {
#pragma unroll
        for (int h = 0; h < 2; h++) {
            int r = aRow + h * 64;
            float4 av = *(const float4*)(Ag + (size_t)r * Kd + k0 + aCol);
            As[aCol + 0][r] = av.x;
            As[aCol + 1][r] = av.y;
            As[aCol + 2][r] = av.z;
            As[aCol + 3][r] = av.w;
        }
#pragma unroll
        for (int h = 0; h < 2; h++) {
            int r = bRow + h * 8;
            *(float4*)(&Bs[r][bCol]) =
                *(const float4*)(Bg + (size_t)(k0 + r) * N + bCol);
        }
        __syncthreads();
#pragma unroll
        for (int k = 0; k < BK; k++) {
            float4 a0 = *(const float4*)(&As[k][trow * TM]);
            float4 a1 = *(const float4*)(&As[k][trow * TM + 4]);
            float4 b0 = *(const float4*)(&Bs[k][tcol * TN]);
            float4 b1 = *(const float4*)(&Bs[k][tcol * TN + 4]);
            float ar[8] = {a0.x, a0.y, a0.z, a0.w, a1.x, a1.y, a1.z, a1.w};
            float br[8] = {b0.x, b0.y, b0.z, b0.w, b1.x, b1.y, b1.z, b1.w};
#pragma unroll
            for (int i = 0; i < TM; i++)
#pragma unroll
                for (int j = 0; j < TN; j++) acc[i][j] += ar[i] * br[j];
        }
        __syncthreads();
    }

    int colBase = bx * BN + tcol * TN;
    float bb[TN];
#pragma unroll
    for (int j = 0; j < TN; j++) bb[j] = bias[colBase + j];
#pragma unroll
    for (int i = 0; i < TM; i++) {
        size_t row = (size_t)by * BM + trow * TM + i;
        float4 o0 = {acc[i][0] + bb[0], acc[i][1] + bb[1],
                     acc[i][2] + bb[2], acc[i][3] + bb[3]};
        float4 o1 = {acc[i][4] + bb[4], acc[i][5] + bb[5],
                     acc[i][6] + bb[6], acc[i][7] + bb[7]};
        *(float4*)(Cm + row * N + colBase)     = o0;
        *(float4*)(Cm + row * N + colBase + 4) = o1;
    }
}

// ---------------- launch ----------------------------------------------------
extern "C" void kernel_launch(void* const* d_in, const int* in_sizes, int n_in,
                              void* d_out, int out_size) {
    const float* x  = (const float*)d_in[0];
    const float* Wq = (const float*)d_in[1];
    const float* bq = (const float*)d_in[2];
    const float* Wk = (const float*)d_in[3];
    const float* bk = (const float*)d_in[4];  (void)bk;  // cancels in softmax
    const float* Wv = (const float*)d_in[5];
    const float* bv = (const float*)d_in[6];
    const float* Wo = (const float*)d_in[7];
    const float* bo = (const float*)d_in[8];
    float* out = (float*)d_out;

    float* pA;
    cudaGetSymbolAddress((void**)&pA, g_A);

    pool_kernel<<<dim3(BSZ, 32), 512>>>(x);
    q_kernel<<<BSZ, 512>>>(Wq, bq);
    qw_kernel<<<dim3(BSZ, NHEAD), 512>>>(Wk);
    score_kernel<<<dim3(BSZ, 32), 256>>>(x);
    softmax_kernel<<<BSZ * NHEAD, 256>>>();
    y_kernel<<<dim3(BSZ, 64, 2), 128>>>(x);
    aproj_kernel<<<dim3(NHEAD, BSZ, 2), 256>>>(Wv, bv);
    combine_kernel<<<BSZ * HH, 512>>>();
    sgemm_bias<<<dim3(4, 512), 256>>>(MROWS, 512, DVV, pA, Wo, bo, out);
}

// round 6
// speedup vs baseline: 6.0521x; 1.1767x over previous
#include <cuda_runtime.h>
#include <cuda_bf16.h>
#include <cstdint>
#include <math.h>

// Problem dims
#define BSZ   16
#define HH    64
#define WWID  64
#define CDIM  512
#define NHEAD 8
#define DKK   64
#define DVV   64
#define PIX   4096
#define MROWS 65536

// ---------------- scratch (device globals; no runtime allocation) ----------
__device__ float g_partial[BSZ * 32 * CDIM];
__device__ float g_q[BSZ * NHEAD * DKK];
__device__ float g_qW[BSZ * NHEAD * CDIM];
__device__ float g_S[BSZ * NHEAD * PIX];
__device__ float g_ah[BSZ * HH * NHEAD * WWID];
__device__ float g_av[BSZ * WWID * NHEAD * HH];
__device__ float g_yh[(size_t)NHEAD * BSZ * HH * CDIM];
__device__ float g_yv[(size_t)NHEAD * BSZ * WWID * CDIM];
__device__ float g_Ah[BSZ * NHEAD * HH * DVV];
__device__ float g_Av[BSZ * NHEAD * WWID * DVV];
__device__ __nv_bfloat16 g_Aext[(size_t)MROWS * 192];  // [Ahi | Alo | Ahi]
__device__ __nv_bfloat16 g_Wext[192 * 512];            // [Whi ; Whi ; Wlo]

__device__ __forceinline__ uint32_t smem_u32(const void* p) {
    uint32_t a;
    asm("{ .reg .u64 t; cvta.to.shared.u64 t, %1; cvt.u32.u64 %0, t; }"
        : "=r"(a) : "l"(p));
    return a;
}

// ---------------- 1) spatial mean pooling ----------------------------------
__global__ __launch_bounds__(512) void pool_kernel(const float* __restrict__ x) {
    int b = blockIdx.x, j = blockIdx.y, c = threadIdx.x;
    const float* xp = x + ((size_t)b * PIX + (size_t)j * 128) * CDIM + c;
    float s = 0.f;
#pragma unroll 8
    for (int p = 0; p < 128; p++) s += xp[(size_t)p * CDIM];
    g_partial[(b * 32 + j) * CDIM + c] = s;
}

// ---------------- 2) q = pooled @ Wq + bq -----------------------------------
__global__ void q_kernel(const float* __restrict__ Wq, const float* __restrict__ bq) {
    int b = blockIdx.x, t = threadIdx.x;
    __shared__ float sp[CDIM];
    float s = 0.f;
#pragma unroll
    for (int j = 0; j < 32; j++) s += g_partial[(b * 32 + j) * CDIM + t];
    sp[t] = s * (1.0f / 4096.0f);
    __syncthreads();
    float acc = bq[t];
#pragma unroll 8
    for (int c = 0; c < CDIM; c++) acc += sp[c] * Wq[c * 512 + t];
    g_q[b * 512 + t] = acc;
}

// ---------------- 3) qW[b,n,c] = scale * sum_k Wk[c, n*64+k] q[b,n,k] ------
__global__ void qw_kernel(const float* __restrict__ Wk) {
    int b = blockIdx.x, n = blockIdx.y, c = threadIdx.x;
    __shared__ float sq[64];
    if (c < 64) sq[c] = g_q[b * 512 + n * 64 + c];
    __syncthreads();
    const float* wr = Wk + (size_t)c * 512 + n * 64;
    float acc = 0.f;
#pragma unroll
    for (int k = 0; k < 64; k++) acc += sq[k] * wr[k];
    g_qW[(b * 8 + n) * 512 + c] = acc * 0.125f;
}

// ---------------- 4) scores: thread-per-pixel, smem-staged x ---------------
// 256 thr, 256 pixels/block. x tile staged through smem (coalesced loads),
// per-thread state = 8 accumulators -> low regs, high occupancy.
__global__ __launch_bounds__(256) void score_kernel(const float* __restrict__ x) {
    extern __shared__ float sdyn[];
    float* sqw = sdyn;            // [8][512]
    float* xs  = sdyn + 4096;     // [256][68]  (stride 68: conflict-free LDS.128)
    int b = blockIdx.x, tid = threadIdx.x;
    int p0 = blockIdx.y * 256;

    for (int i = tid; i < 4096; i += 256)
        sqw[i] = g_qW[(size_t)b * 4096 + i];

    float acc[8] = {0.f, 0.f, 0.f, 0.f, 0.f, 0.f, 0.f, 0.f};

    for (int ch = 0; ch < 8; ch++) {
        __syncthreads();
        // stage x[p0..p0+255][ch*64..+64] -> xs (coalesced: 16 thr per row)
#pragma unroll
        for (int i = 0; i < 16; i++) {
            int idx = tid + i * 256;
            int p = idx >> 4, c4 = idx & 15;
            *(float4*)(xs + p * 68 + c4 * 4) =
                *(const float4*)(x + ((size_t)b * PIX + p0 + p) * CDIM + ch * 64 + c4 * 4);
        }
        __syncthreads();
#pragma unroll 4
        for (int c4 = 0; c4 < 16; c4++) {
            float4 xv = *(const float4*)(xs + tid * 68 + c4 * 4);
#pragma unroll
            for (int n = 0; n < 8; n++) {
                float4 w = *(const float4*)(sqw + n * 512 + ch * 64 + c4 * 4);
                acc[n] += xv.x * w.x + xv.y * w.y + xv.z * w.z + xv.w * w.w;
            }
        }
    }
#pragma unroll
    for (int n = 0; n < 8; n++)
        g_S[(size_t)(b * 8 + n) * PIX + p0 + tid] = acc[n];
}

// ---------------- 5) dual softmax per (b,n), write transposed layouts ------
__global__ __launch_bounds__(256) void softmax_kernel() {
    int bn = blockIdx.x;
    int b = bn >> 3, n = bn & 7;
    int tid = threadIdx.x, w = tid >> 5, l = tid & 31;
    __shared__ float ss[4096];
    for (int i = tid; i < 4096; i += 256) ss[i] = g_S[(size_t)bn * 4096 + i];
    __syncthreads();

    for (int h = w; h < 64; h += 8) {
        float x0 = ss[h * 64 + l], x1 = ss[h * 64 + 32 + l];
        float m = fmaxf(x0, x1);
#pragma unroll
        for (int o = 16; o > 0; o >>= 1)
            m = fmaxf(m, __shfl_xor_sync(0xffffffffu, m, o));
        float e0 = __expf(x0 - m), e1 = __expf(x1 - m);
        float sum = e0 + e1;
#pragma unroll
        for (int o = 16; o > 0; o >>= 1)
            sum += __shfl_xor_sync(0xffffffffu, sum, o);
        float inv = 1.0f / sum;
        float* dst = g_ah + ((size_t)(b * 64 + h) * 8 + n) * 64;
        dst[l] = e0 * inv;
        dst[32 + l] = e1 * inv;
    }

    if (tid < 64) {
        int c = tid;
        float m = -1e30f;
#pragma unroll 8
        for (int h = 0; h < 64; h++) m = fmaxf(m, ss[h * 64 + c]);
        float sum = 0.f;
#pragma unroll 8
        for (int h = 0; h < 64; h++) sum += __expf(ss[h * 64 + c] - m);
        float inv = 1.0f / sum;
        float* dst = g_av + ((size_t)(b * 64 + c) * 8 + n) * 64;
#pragma unroll 8
        for (int h = 0; h < 64; h++)
            dst[h] = __expf(ss[h * 64 + c] - m) * inv;
    }
}

// ---------------- 6) y_h / y_v: weighted sums of x rows --------------------
__global__ __launch_bounds__(128) void y_kernel(const float* __restrict__ x) {
    int b = blockIdx.x, s = blockIdx.y, path = blockIdx.z;
    int tid = threadIdx.x;
    __shared__ float sa[512];
    const float* asrc = (path ? g_av : g_ah) + (size_t)(b * 64 + s) * 512;
    for (int i = tid; i < 512; i += 128) sa[i] = asrc[i];
    __syncthreads();

    size_t base = (size_t)b * PIX * CDIM +
                  (path ? (size_t)s * CDIM : (size_t)s * 64 * CDIM);
    size_t stride4 = (path ? (size_t)64 * CDIM : (size_t)CDIM) / 4;
    const float4* xp = (const float4*)(x) + base / 4 + tid;

    float4 acc[8];
#pragma unroll
    for (int n = 0; n < 8; n++) acc[n] = make_float4(0.f, 0.f, 0.f, 0.f);

#pragma unroll 8
    for (int j = 0; j < 64; j++) {
        float4 xv = xp[j * stride4];
#pragma unroll
        for (int n = 0; n < 8; n++) {
            float f = sa[n * 64 + j];
            acc[n].x += f * xv.x;
            acc[n].y += f * xv.y;
            acc[n].z += f * xv.z;
            acc[n].w += f * xv.w;
        }
    }
    float* yout = path ? g_yv : g_yh;
#pragma unroll
    for (int n = 0; n < 8; n++)
        ((float4*)(yout + ((size_t)(n * 1024 + b * 64 + s)) * 512))[tid] = acc[n];
}

// ---------------- 7) project y -> A_h / A_v (per-head 64-col GEMM) ---------
__global__ __launch_bounds__(256) void aproj_kernel(
    const float* __restrict__ Wv, const float* __restrict__ bv)
{
    int n = blockIdx.x, b = blockIdx.y, path = blockIdx.z;
    const float* Y = (path ? g_yv : g_yh) + ((size_t)(n * 1024 + b * 64)) * 512;
    float* outp = (path ? g_Av : g_Ah) + (size_t)(b * 8 + n) * 4096;
    __shared__ float sY[64][32];
    __shared__ float sW[32][64];
    int tid = threadIdx.x;
    int tr = tid >> 4, tc = tid & 15;
    float acc[4][4];
#pragma unroll
    for (int i = 0; i < 4; i++)
#pragma unroll
        for (int j = 0; j < 4; j++) acc[i][j] = 0.f;

    for (int k0 = 0; k0 < 512; k0 += 32) {
        for (int i = tid; i < 512; i += 256) {
            int r = i >> 3, c4 = i & 7;
            *(float4*)&sY[r][c4 * 4] =
                *(const float4*)(Y + (size_t)r * 512 + k0 + c4 * 4);
        }
        for (int i = tid; i < 512; i += 256) {
            int r = i >> 4, c4 = i & 15;
            *(float4*)&sW[r][c4 * 4] =
                *(const float4*)(Wv + (size_t)(k0 + r) * 512 + n * 64 + c4 * 4);
        }
        __syncthreads();
#pragma unroll
        for (int k = 0; k < 32; k++) {
            float4 bw = *(float4*)&sW[k][tc * 4];
            float a0 = sY[tr * 4 + 0][k], a1 = sY[tr * 4 + 1][k];
            float a2 = sY[tr * 4 + 2][k], a3 = sY[tr * 4 + 3][k];
            acc[0][0] += a0 * bw.x; acc[0][1] += a0 * bw.y; acc[0][2] += a0 * bw.z; acc[0][3] += a0 * bw.w;
            acc[1][0] += a1 * bw.x; acc[1][1] += a1 * bw.y; acc[1][2] += a1 * bw.z; acc[1][3] += a1 * bw.w;
            acc[2][0] += a2 * bw.x; acc[2][1] += a2 * bw.y; acc[2][2] += a2 * bw.z; acc[2][3] += a2 * bw.w;
            acc[3][0] += a3 * bw.x; acc[3][1] += a3 * bw.y; acc[3][2] += a3 * bw.z; acc[3][3] += a3 * bw.w;
        }
        __syncthreads();
    }
    float bb[4];
#pragma unroll
    for (int j = 0; j < 4; j++) bb[j] = bv[n * 64 + tc * 4 + j];
#pragma unroll
    for (int i = 0; i < 4; i++)
#pragma unroll
        for (int j = 0; j < 4; j++)
            outp[(tr * 4 + i) * 64 + tc * 4 + j] = acc[i][j] + bb[j];
}

// ---------------- 8) Wext = [hi(Wo); hi(Wo); lo(Wo)] -----------------------
__global__ void wext_kernel(const float* __restrict__ Wo) {
    int r = blockIdx.x, n = threadIdx.x;   // 192 blocks, 512 thr
    int src = (r < 128) ? (r & 63) : (r - 128);
    float v = Wo[(size_t)src * 512 + n];
    __nv_bfloat16 hi = __float2bfloat16(v);
    g_Wext[r * 512 + n] = (r < 128) ? hi
                                    : __float2bfloat16(v - __bfloat162float(hi));
}

// ---------------- 9) combine -> Aext bf16 [hi|lo|hi] ------------------------
__global__ __launch_bounds__(512) void combine_kernel() {
    int b = blockIdx.x >> 6, h = blockIdx.x & 63;
    int tid = threadIdx.x;
    __shared__ float sAh[NHEAD * DVV];
    {
        int n = tid >> 6, v = tid & 63;
        sAh[tid] = g_Ah[((size_t)(b * 8 + n) * 64 + h) * 64 + v];
    }
    __syncthreads();
    int v = tid & 63, wg = tid >> 6;
    for (int wc = wg; wc < 64; wc += 8) {
        float acc = 0.f;
#pragma unroll
        for (int n = 0; n < NHEAD; n++)
            acc += sAh[n * 64 + v] *
                   g_Av[((size_t)(b * 8 + n) * 64 + wc) * 64 + v];
        size_t row = ((size_t)(b * 64 + h)) * 64 + wc;
        __nv_bfloat16 hi = __float2bfloat16(acc);
        __nv_bfloat16 lo = __float2bfloat16(acc - __bfloat162float(hi));
        g_Aext[row * 192 + v]       = hi;
        g_Aext[row * 192 + 64 + v]  = lo;
        g_Aext[row * 192 + 128 + v] = hi;
    }
}

// ---------------- 10) bf16 mma.sync GEMM: C = Aext @ Wext + bias -----------
// M=65536, N=512, K=192. Block tile 128x128, 8 warps (2x4), warp tile 64x32.
__global__ __launch_bounds__(256) void mma_gemm_out(
    const float* __restrict__ bias, float* __restrict__ C)
{
    __shared__ __align__(16) __nv_bfloat16 smA[128 * 72];  // stride 72
    __shared__ __align__(16) __nv_bfloat16 smB[64 * 136];  // stride 136
    int tid = threadIdx.x, lane = tid & 31, wid = tid >> 5;
    int wm = wid >> 2, wn = wid & 3;
    size_t m0 = (size_t)blockIdx.y * 128;
    int n0 = blockIdx.x * 128;

    float acc[4][4][4];
#pragma unroll
    for (int i = 0; i < 4; i++)
#pragma unroll
        for (int j = 0; j < 4; j++)
#pragma unroll
            for (int k = 0; k < 4; k++) acc[i][j][k] = 0.f;

    for (int kc = 0; kc < 192; kc += 64) {
#pragma unroll
        for (int i = 0; i < 4; i++) {
            int idx = tid + i * 256;
            int r = idx >> 3, c8 = idx & 7;
            *(float4*)(smA + r * 72 + c8 * 8) =
                *(const float4*)(g_Aext + (m0 + r) * 192 + kc + c8 * 8);
        }
#pragma unroll
        for (int i = 0; i < 4; i++) {
            int idx = tid + i * 256;
            int r = idx >> 4, c8 = idx & 15;
            *(float4*)(smB + r * 136 + c8 * 8) =
                *(const float4*)(g_Wext + (size_t)(kc + r) * 512 + n0 + c8 * 8);
        }
        __syncthreads();

#pragma unroll
        for (int ks = 0; ks < 4; ks++) {
            uint32_t af[4][4];
#pragma unroll
            for (int mi = 0; mi < 4; mi++) {
                uint32_t addr = smem_u32(
                    smA + (wm * 64 + mi * 16 + (lane & 15)) * 72 +
                    ks * 16 + (lane >> 4) * 8);
                asm volatile(
                    "ldmatrix.sync.aligned.m8n8.x4.shared.b16 {%0,%1,%2,%3}, [%4];"
                    : "=r"(af[mi][0]), "=r"(af[mi][1]),
                      "=r"(af[mi][2]), "=r"(af[mi][3])
                    : "r"(addr));
            }
            uint32_t bfr[2][4];
#pragma unroll
            for (int bi = 0; bi < 2; bi++) {
                int nb = wn * 32 + bi * 16;
                uint32_t addr = smem_u32(
                    smB + (ks * 16 + (lane & 7) + ((lane >> 3) & 1) * 8) * 136 +
                    nb + (lane >> 4) * 8);
                asm volatile(
                    "ldmatrix.sync.aligned.m8n8.x4.trans.shared.b16 {%0,%1,%2,%3}, [%4];"
                    : "=r"(bfr[bi][0]), "=r"(bfr[bi][1]),
                      "=r"(bfr[bi][2]), "=r"(bfr[bi][3])
                    : "r"(addr));
            }
#pragma unroll
            for (int mi = 0; mi < 4; mi++) {
#pragma unroll
                for (int ni = 0; ni < 4; ni++) {
                    uint32_t b0 = bfr[ni >> 1][(ni & 1) * 2];
                    uint32_t b1 = bfr[ni >> 1][(ni & 1) * 2 + 1];
                    asm volatile(
                        "mma.sync.aligned.m16n8k16.row.col.f32.bf16.bf16.f32 "
                        "{%0,%1,%2,%3}, {%4,%5,%6,%7}, {%8,%9}, {%0,%1,%2,%3};"
                        : "+f"(acc[mi][ni][0]), "+f"(acc[mi][ni][1]),
                          "+f"(acc[mi][ni][2]), "+f"(acc[mi][ni][3])
                        : "r"(af[mi][0]), "r"(af[mi][1]),
                          "r"(af[mi][2]), "r"(af[mi][3]),
                          "r"(b0), "r"(b1));
                }
            }
        }
        __syncthreads();
    }

    int g = lane >> 2, t = lane & 3;
#pragma unroll
    for (int mi = 0; mi < 4; mi++) {
#pragma unroll
        for (int ni = 0; ni < 4; ni++) {
            size_t row = m0 + wm * 64 + mi * 16 + g;
            int col = n0 + wn * 32 + ni * 8 + t * 2;
            float b0 = bias[col], b1 = bias[col + 1];
            float2 o0 = {acc[mi][ni][0] + b0, acc[mi][ni][1] + b1};
            float2 o1 = {acc[mi][ni][2] + b0, acc[mi][ni][3] + b1};
            *(float2*)(C + row * 512 + col) = o0;
            *(float2*)(C + (row + 8) * 512 + col) = o1;
        }
    }
}

// ---------------- launch ----------------------------------------------------
extern "C" void kernel_launch(void* const* d_in, const int* in_sizes, int n_in,
                              void* d_out, int out_size) {
    const float* x  = (const float*)d_in[0];
    const float* Wq = (const float*)d_in[1];
    const float* bq = (const float*)d_in[2];
    const float* Wk = (const float*)d_in[3];
    const float* bk = (const float*)d_in[4];  (void)bk;  // cancels in softmax
    const float* Wv = (const float*)d_in[5];
    const float* bv = (const float*)d_in[6];
    const float* Wo = (const float*)d_in[7];
    const float* bo = (const float*)d_in[8];
    float* out = (float*)d_out;

    const int SCORE_SMEM = (4096 + 256 * 68) * 4;   // 86016 B
    cudaFuncSetAttribute(score_kernel,
                         cudaFuncAttributeMaxDynamicSharedMemorySize, SCORE_SMEM);

    pool_kernel<<<dim3(BSZ, 32), 512>>>(x);
    q_kernel<<<BSZ, 512>>>(Wq, bq);
    qw_kernel<<<dim3(BSZ, NHEAD), 512>>>(Wk);
    wext_kernel<<<192, 512>>>(Wo);
    score_kernel<<<dim3(BSZ, 16), 256, SCORE_SMEM>>>(x);
    softmax_kernel<<<BSZ * NHEAD, 256>>>();
    y_kernel<<<dim3(BSZ, 64, 2), 128>>>(x);
    aproj_kernel<<<dim3(NHEAD, BSZ, 2), 256>>>(Wv, bv);
    combine_kernel<<<BSZ * HH, 512>>>();
    mma_gemm_out<<<dim3(4, 512), 256>>>(bo, out);
}